// round 1
// baseline (speedup 1.0000x reference)
#include <cuda_runtime.h>

// ---------------------------------------------------------------------------
// HopfieldPooling restructured:
//   keys   = key_param @ Wk + bk                    [32,1024]
//   values = keys @ Wv + bv                         [32,1024]
//   P[c,(h,s)]   = scale * sum_e Wq[c,hE+e]*keys[s,hE+e]        [1024,512]
//   sbias[(h,s)] = scale * sum_e bq[hE+e]*keys[s,hE+e]          [512]
//   scores = query @ P + sbias                      [32768,512]  (GEMM 1)
//   A = sparsemax_over_s(scores)                    (in place, warp/32)
//   U2[h,g,s,m] = sum_d values[s,hE+d]*Wo[g*64+d,m]             [16,16,32,1024]
//   out[b,i,m] = sum_{g,s} A[b,(i%256)*16+g, h=i>>8, s]*U2[h,g,s,m] + bo[m]
//                                                   (GEMM 2, gathered A)
// Total ~70 GFLOP fp32 (vs 142 naive).
// ---------------------------------------------------------------------------

#define DM    1024
#define NHD   16
#define HDM   64
#define SPAT  32
#define NROWS 32768       // 8*4096
#define NSC   512         // H*S
#define SCALEF 0.125f     // 1/sqrt(64)

static __device__ float g_keys[SPAT * DM];
static __device__ float g_keysT[DM * SPAT];
static __device__ float g_values[SPAT * DM];
static __device__ float g_P[(size_t)DM * NSC];
static __device__ float g_sbias[NSC];
static __device__ float g_U2[(size_t)NHD * 16 * SPAT * DM];   // 33.5 MB
static __device__ float g_scores[(size_t)NROWS * NSC];        // 64 MB

// ---------------- prep: keys = key_param @ Wk + bk -------------------------
__global__ void k_keys(const float* __restrict__ kp,
                       const float* __restrict__ Wk,
                       const float* __restrict__ bk) {
    int s = blockIdx.y;
    int j = blockIdx.x * 256 + threadIdx.x;
    __shared__ float xs[DM];
    for (int c = threadIdx.x; c < DM; c += 256) xs[c] = kp[s * DM + c];
    __syncthreads();
    float acc = bk[j];
#pragma unroll 4
    for (int c = 0; c < DM; c++) acc = fmaf(xs[c], Wk[(size_t)c * DM + j], acc);
    g_keys[s * DM + j]  = acc;
    g_keysT[j * SPAT + s] = acc;
}

// ---------------- prep: values = keys @ Wv + bv ----------------------------
__global__ void k_values(const float* __restrict__ Wv,
                         const float* __restrict__ bv) {
    int s = blockIdx.y;
    int j = blockIdx.x * 256 + threadIdx.x;
    __shared__ float xs[DM];
    for (int c = threadIdx.x; c < DM; c += 256) xs[c] = g_keys[s * DM + c];
    __syncthreads();
    float acc = bv[j];
#pragma unroll 4
    for (int c = 0; c < DM; c++) acc = fmaf(xs[c], Wv[(size_t)c * DM + j], acc);
    g_values[s * DM + j] = acc;
}

// ---------------- prep: P[c, hs] ------------------------------------------
__global__ void k_P(const float* __restrict__ Wq) {
    int c = blockIdx.x;
    __shared__ float wq[DM];
    wq[threadIdx.x]       = Wq[(size_t)c * DM + threadIdx.x];
    wq[threadIdx.x + 512] = Wq[(size_t)c * DM + threadIdx.x + 512];
    __syncthreads();
    int hs = threadIdx.x;
    int h = hs >> 5, s = hs & 31;
    float acc = 0.f;
#pragma unroll 8
    for (int e = 0; e < HDM; e++)
        acc = fmaf(wq[h * HDM + e], g_keysT[(h * HDM + e) * SPAT + s], acc);
    g_P[(size_t)c * NSC + hs] = SCALEF * acc;
}

// ---------------- prep: sbias[hs] ------------------------------------------
__global__ void k_sbias(const float* __restrict__ bq) {
    int hs = threadIdx.x;
    int h = hs >> 5, s = hs & 31;
    float acc = 0.f;
#pragma unroll 8
    for (int e = 0; e < HDM; e++)
        acc = fmaf(bq[h * HDM + e], g_keysT[(h * HDM + e) * SPAT + s], acc);
    g_sbias[hs] = SCALEF * acc;
}

// ---------------- prep: U2[h,g,s,m] ----------------------------------------
__global__ void k_U2(const float* __restrict__ Wo) {
    int hg = blockIdx.y;
    int h = hg >> 4, g = hg & 15;
    int m = blockIdx.x * 256 + threadIdx.x;
    __shared__ float vs[SPAT * HDM];   // [s][d]
    for (int idx = threadIdx.x; idx < SPAT * HDM; idx += 256) {
        int s = idx >> 6, d = idx & 63;
        vs[idx] = g_values[s * DM + h * HDM + d];
    }
    __syncthreads();
    float acc[SPAT];
#pragma unroll
    for (int s = 0; s < SPAT; s++) acc[s] = 0.f;
    for (int d = 0; d < HDM; d++) {
        float w = Wo[(size_t)(g * HDM + d) * DM + m];
#pragma unroll
        for (int s = 0; s < SPAT; s++) acc[s] = fmaf(vs[s * HDM + d], w, acc[s]);
    }
    size_t base = (size_t)hg * SPAT * DM + m;
#pragma unroll
    for (int s = 0; s < SPAT; s++) g_U2[base + (size_t)s * DM] = acc[s];
}

// ---------------- GEMM 1: scores = query @ P + sbias -----------------------
// M=32768, N=512, K=1024. 128x128 tiles, BK=8, 256 thr, 8x8/thread, dbl-buf.
__global__ __launch_bounds__(256, 2) void sgemm_scores(const float* __restrict__ A) {
    const int BK = 8;
    int n0 = blockIdx.x * 128;
    int m0 = blockIdx.y * 128;
    __shared__ float As[2][BK][128];
    __shared__ float Bs[2][BK][128];
    int t = threadIdx.x;
    int arow = t >> 1;
    int aq   = (t & 1) * 4;
    int brow = t >> 5;
    int bcol = (t & 31) * 4;
    int tx = (t & 15) * 8;
    int ty = (t >> 4) * 8;

    const float* Aptr = A + (size_t)(m0 + arow) * DM + aq;
    const float* Bptr = g_P + (size_t)brow * NSC + n0 + bcol;

    float4 af = *(const float4*)Aptr;
    float4 bf = *(const float4*)Bptr;

    float acc[8][8];
#pragma unroll
    for (int i = 0; i < 8; i++)
#pragma unroll
        for (int j = 0; j < 8; j++) acc[i][j] = 0.f;

    As[0][aq + 0][arow] = af.x; As[0][aq + 1][arow] = af.y;
    As[0][aq + 2][arow] = af.z; As[0][aq + 3][arow] = af.w;
    *(float4*)&Bs[0][brow][bcol] = bf;
    __syncthreads();

    const int KT = DM / BK;
    int buf = 0;
    for (int kt = 0; kt < KT; kt++) {
        if (kt + 1 < KT) {
            af = *(const float4*)(Aptr + (kt + 1) * BK);
            bf = *(const float4*)(Bptr + (size_t)(kt + 1) * BK * NSC);
        }
#pragma unroll
        for (int kk = 0; kk < BK; kk++) {
            float a[8], b2[8];
            *(float4*)&a[0]  = *(float4*)&As[buf][kk][ty];
            *(float4*)&a[4]  = *(float4*)&As[buf][kk][ty + 4];
            *(float4*)&b2[0] = *(float4*)&Bs[buf][kk][tx];
            *(float4*)&b2[4] = *(float4*)&Bs[buf][kk][tx + 4];
#pragma unroll
            for (int i = 0; i < 8; i++)
#pragma unroll
                for (int j = 0; j < 8; j++)
                    acc[i][j] = fmaf(a[i], b2[j], acc[i][j]);
        }
        if (kt + 1 < KT) {
            buf ^= 1;
            As[buf][aq + 0][arow] = af.x; As[buf][aq + 1][arow] = af.y;
            As[buf][aq + 2][arow] = af.z; As[buf][aq + 3][arow] = af.w;
            *(float4*)&Bs[buf][brow][bcol] = bf;
            __syncthreads();
        }
    }
#pragma unroll
    for (int i = 0; i < 8; i++) {
        int row = m0 + ty + i;
        float* orow = g_scores + (size_t)row * NSC + n0;
#pragma unroll
        for (int j = 0; j < 8; j += 4) {
            float4 v;
            v.x = acc[i][j + 0] + g_sbias[n0 + tx + j + 0];
            v.y = acc[i][j + 1] + g_sbias[n0 + tx + j + 1];
            v.z = acc[i][j + 2] + g_sbias[n0 + tx + j + 2];
            v.w = acc[i][j + 3] + g_sbias[n0 + tx + j + 3];
            *(float4*)&orow[tx + j] = v;
        }
    }
}

// ---------------- sparsemax over S=32, one warp per (row, head) -------------
__global__ void k_sparsemax() {
    int W = blockIdx.x * 8 + (threadIdx.x >> 5);   // W = r*16 + h
    int lane = threadIdx.x & 31;
    size_t base = (size_t)W * 32;
    float z = g_scores[base + lane];
    float v = z;
    // bitonic sort, descending
#pragma unroll
    for (int k = 2; k <= 32; k <<= 1)
#pragma unroll
        for (int j = k >> 1; j > 0; j >>= 1) {
            float o = __shfl_xor_sync(0xffffffffu, v, j);
            bool up = ((lane & k) == 0) == ((lane & j) == 0);
            v = up ? fmaxf(v, o) : fminf(v, o);
        }
    // inclusive prefix sum of sorted values
    float cum = v;
#pragma unroll
    for (int d = 1; d < 32; d <<= 1) {
        float tt = __shfl_up_sync(0xffffffffu, cum, d);
        if (lane >= d) cum += tt;
    }
    bool sup = (1.0f + (float)(lane + 1) * v) > cum;
    unsigned bal = __ballot_sync(0xffffffffu, sup);
    int ksup = __popc(bal);
    float cumsel = __shfl_sync(0xffffffffu, cum, ksup - 1);
    float tau = (cumsel - 1.0f) / (float)ksup;
    g_scores[base + lane] = fmaxf(z - tau, 0.0f);
}

// ---------------- GEMM 2: out = gatherA @ U2[h] + bo ------------------------
// M=32768, N=1024, K=512. A rows gathered from g_scores (mix layout).
__global__ __launch_bounds__(256, 2) void sgemm_out(float* __restrict__ out,
                                                    const float* __restrict__ bo) {
    const int BK = 8;
    int n0 = blockIdx.x * 128;
    int m0 = blockIdx.y * 128;
    __shared__ float As[2][BK][128];
    __shared__ float Bs[2][BK][128];
    int t = threadIdx.x;
    int arow = t >> 1;
    int aq   = (t & 1) * 4;
    int brow = t >> 5;
    int bcol = (t & 31) * 4;
    int tx = (t & 15) * 8;
    int ty = (t >> 4) * 8;

    // gather-A per-thread constants
    int r  = m0 + arow;
    int bb = r >> 12;
    int ii = r & 4095;
    int hh = ii >> 8;
    size_t rowbase = ((size_t)((bb << 12) + ((ii & 255) << 4))) * NSC + (hh << 5);

    int hblk = (m0 & 4095) >> 8;
    const float* Bbase = g_U2 + (size_t)hblk * NSC * DM;
    const float* Bptr  = Bbase + (size_t)brow * DM + n0 + bcol;

    // kt = 0 loads
    int kk0 = aq;                       // g = 0, s = aq
    float4 af = *(const float4*)(g_scores + rowbase + (size_t)(kk0 >> 5) * NSC + (kk0 & 31));
    float4 bf = *(const float4*)Bptr;

    float acc[8][8];
#pragma unroll
    for (int i = 0; i < 8; i++)
#pragma unroll
        for (int j = 0; j < 8; j++) acc[i][j] = 0.f;

    As[0][aq + 0][arow] = af.x; As[0][aq + 1][arow] = af.y;
    As[0][aq + 2][arow] = af.z; As[0][aq + 3][arow] = af.w;
    *(float4*)&Bs[0][brow][bcol] = bf;
    __syncthreads();

    const int KT = NSC / BK;            // 64
    int buf = 0;
    for (int kt = 0; kt < KT; kt++) {
        if (kt + 1 < KT) {
            int kkn = (kt + 1) * BK + aq;
            af = *(const float4*)(g_scores + rowbase + (size_t)(kkn >> 5) * NSC + (kkn & 31));
            bf = *(const float4*)(Bptr + (size_t)(kt + 1) * BK * DM);
        }
#pragma unroll
        for (int kk = 0; kk < BK; kk++) {
            float a[8], b2[8];
            *(float4*)&a[0]  = *(float4*)&As[buf][kk][ty];
            *(float4*)&a[4]  = *(float4*)&As[buf][kk][ty + 4];
            *(float4*)&b2[0] = *(float4*)&Bs[buf][kk][tx];
            *(float4*)&b2[4] = *(float4*)&Bs[buf][kk][tx + 4];
#pragma unroll
            for (int i = 0; i < 8; i++)
#pragma unroll
                for (int j = 0; j < 8; j++)
                    acc[i][j] = fmaf(a[i], b2[j], acc[i][j]);
        }
        if (kt + 1 < KT) {
            buf ^= 1;
            As[buf][aq + 0][arow] = af.x; As[buf][aq + 1][arow] = af.y;
            As[buf][aq + 2][arow] = af.z; As[buf][aq + 3][arow] = af.w;
            *(float4*)&Bs[buf][brow][bcol] = bf;
            __syncthreads();
        }
    }
#pragma unroll
    for (int i = 0; i < 8; i++) {
        int row = m0 + ty + i;
        float* orow = out + (size_t)row * DM + n0;
#pragma unroll
        for (int j = 0; j < 8; j += 4) {
            float4 v;
            v.x = acc[i][j + 0] + bo[n0 + tx + j + 0];
            v.y = acc[i][j + 1] + bo[n0 + tx + j + 1];
            v.z = acc[i][j + 2] + bo[n0 + tx + j + 2];
            v.w = acc[i][j + 3] + bo[n0 + tx + j + 3];
            *(float4*)&orow[tx + j] = v;
        }
    }
}

// ---------------------------------------------------------------------------
extern "C" void kernel_launch(void* const* d_in, const int* in_sizes, int n_in,
                              void* d_out, int out_size) {
    (void)in_sizes; (void)n_in; (void)out_size;
    const float* query = (const float*)d_in[0];
    const float* kp    = (const float*)d_in[1];
    const float* Wq    = (const float*)d_in[2];
    const float* bq    = (const float*)d_in[3];
    const float* Wk    = (const float*)d_in[4];
    const float* bk    = (const float*)d_in[5];
    const float* Wv    = (const float*)d_in[6];
    const float* bv    = (const float*)d_in[7];
    const float* Wo    = (const float*)d_in[8];
    const float* bo    = (const float*)d_in[9];
    float* out = (float*)d_out;

    k_keys  <<<dim3(4, SPAT), 256>>>(kp, Wk, bk);
    k_values<<<dim3(4, SPAT), 256>>>(Wv, bv);
    k_P     <<<DM, 512>>>(Wq);
    k_sbias <<<1, 512>>>(bq);
    k_U2    <<<dim3(4, 256), 256>>>(Wo);

    sgemm_scores<<<dim3(NSC / 128, NROWS / 128), 256>>>(query);
    k_sparsemax <<<(NROWS * NHD) / 8, 256>>>();
    sgemm_out   <<<dim3(DM / 128, NROWS / 128), 256>>>(out, bo);
}

// round 4
// speedup vs baseline: 1.7610x; 1.7610x over previous
#include <cuda_runtime.h>
#include <cuda_bf16.h>
#include <cstdint>

// ---------------------------------------------------------------------------
// HopfieldPooling via mma.sync (HMMA) bf16 split-GEMMs (sm_103-safe PTX):
//   keys   = key_param @ Wk + bk                      [32,1024]  (fp32, tiny)
//   values = keys @ Wv + bv                           [32,1024]  (fp32, tiny)
//   PT[hs,c]  = scale * sum_e Wq[c,hE+e]*keys[s,hE+e]   -> bf16 hi/lo [512,1024]
//   sbias[hs] = scale * sum_e bq[hE+e]*keys[s,hE+e]     (fp32)
//   qhi/qlo   = bf16 split of query                     [32768,1024]
//   scores = q @ PT^T + sbias      (TC GEMM1, fp32 out)  [32768,512]
//   sparsemax over s (warp/32) -> writes A2 in mix layout, bf16 hi/lo
//   U2T[h][m][g*32+s] = sum_d values[s,hE+d]*Wo[g*64+d,m] -> bf16 hi/lo
//   out = A2 @ U2T[h]^T + bo       (TC GEMM2, fp32 out)  [32768,1024]
// Split math: x = hi + lo (bf16 each); x*y ~= hi*hi' + hi*lo' + lo*hi'
// ---------------------------------------------------------------------------

#define DM    1024
#define NHD   16
#define HDM   64
#define SPAT  32
#define NROWS 32768
#define NSC   512
#define SCALEF 0.125f

static __device__ float g_keys[SPAT * DM];
static __device__ float g_keysT[DM * SPAT];
static __device__ float g_values[SPAT * DM];
static __device__ float g_sbias[NSC];
static __device__ float g_scores[(size_t)NROWS * NSC];                 // 64 MB

static __device__ __nv_bfloat16 g_qhi[(size_t)NROWS * DM];             // 64 MB
static __device__ __nv_bfloat16 g_qlo[(size_t)NROWS * DM];             // 64 MB
static __device__ __nv_bfloat16 g_pthi[(size_t)NSC * DM];              // 1 MB
static __device__ __nv_bfloat16 g_ptlo[(size_t)NSC * DM];
static __device__ __nv_bfloat16 g_u2thi[(size_t)NHD * DM * NSC];       // 16 MB
static __device__ __nv_bfloat16 g_u2tlo[(size_t)NHD * DM * NSC];
static __device__ __nv_bfloat16 g_a2hi[(size_t)NROWS * NSC];           // 32 MB
static __device__ __nv_bfloat16 g_a2lo[(size_t)NROWS * NSC];

// ======================= PTX helpers =======================================
__device__ __forceinline__ uint32_t smem_u32(const void* p) {
    uint32_t a;
    asm("{ .reg .u64 t; cvta.to.shared.u64 t, %1; cvt.u32.u64 %0, t; }" : "=r"(a) : "l"(p));
    return a;
}
#define CP16(dst, src) \
    asm volatile("cp.async.cg.shared.global [%0], [%1], 16;" :: "r"(dst), "l"(src))
#define CP_COMMIT() asm volatile("cp.async.commit_group;")
#define CP_WAIT(n)  asm volatile("cp.async.wait_group %0;" :: "n"(n) : "memory")

#define LDSM4(r, addr) \
    asm volatile("ldmatrix.sync.aligned.m8n8.x4.shared.b16 {%0,%1,%2,%3}, [%4];" \
        : "=r"((r)[0]), "=r"((r)[1]), "=r"((r)[2]), "=r"((r)[3]) : "r"(addr))

#define MMA16816(c, a, b) \
    asm volatile("mma.sync.aligned.m16n8k16.row.col.f32.bf16.bf16.f32 " \
        "{%0,%1,%2,%3}, {%4,%5,%6,%7}, {%8,%9}, {%0,%1,%2,%3};" \
        : "+f"((c)[0]), "+f"((c)[1]), "+f"((c)[2]), "+f"((c)[3]) \
        : "r"((a)[0]), "r"((a)[1]), "r"((a)[2]), "r"((a)[3]), \
          "r"((b)[0]), "r"((b)[1]))

__device__ __forceinline__ uint32_t swz(uint32_t off) {
    return off ^ ((off >> 3) & 0x70u);
}

// ======================= prep kernels ======================================
__global__ void k_keys(const float* __restrict__ kp, const float* __restrict__ Wk,
                       const float* __restrict__ bk) {
    int s = blockIdx.y;
    int j = blockIdx.x * 256 + threadIdx.x;
    __shared__ float xs[DM];
    for (int c = threadIdx.x; c < DM; c += 256) xs[c] = kp[s * DM + c];
    __syncthreads();
    float acc = bk[j];
#pragma unroll 4
    for (int c = 0; c < DM; c++) acc = fmaf(xs[c], Wk[(size_t)c * DM + j], acc);
    g_keys[s * DM + j] = acc;
    g_keysT[j * SPAT + s] = acc;
}

__global__ void k_values(const float* __restrict__ Wv, const float* __restrict__ bv) {
    int s = blockIdx.y;
    int j = blockIdx.x * 256 + threadIdx.x;
    __shared__ float xs[DM];
    for (int c = threadIdx.x; c < DM; c += 256) xs[c] = g_keys[s * DM + c];
    __syncthreads();
    float acc = bv[j];
#pragma unroll 4
    for (int c = 0; c < DM; c++) acc = fmaf(xs[c], Wv[(size_t)c * DM + j], acc);
    g_values[s * DM + j] = acc;
}

__global__ void k_P(const float* __restrict__ Wq) {
    int c = blockIdx.x;
    __shared__ float wq[DM];
    wq[threadIdx.x]       = Wq[(size_t)c * DM + threadIdx.x];
    wq[threadIdx.x + 512] = Wq[(size_t)c * DM + threadIdx.x + 512];
    __syncthreads();
    int hs = threadIdx.x;
    int h = hs >> 5, s = hs & 31;
    float acc = 0.f;
#pragma unroll 8
    for (int e = 0; e < HDM; e++)
        acc = fmaf(wq[h * HDM + e], g_keysT[(h * HDM + e) * SPAT + s], acc);
    float v = SCALEF * acc;
    __nv_bfloat16 hi = __float2bfloat16(v);
    g_pthi[(size_t)hs * DM + c] = hi;
    g_ptlo[(size_t)hs * DM + c] = __float2bfloat16(v - __bfloat162float(hi));
}

__global__ void k_sbias(const float* __restrict__ bq) {
    int hs = threadIdx.x;
    int h = hs >> 5, s = hs & 31;
    float acc = 0.f;
#pragma unroll 8
    for (int e = 0; e < HDM; e++)
        acc = fmaf(bq[h * HDM + e], g_keysT[(h * HDM + e) * SPAT + s], acc);
    g_sbias[hs] = SCALEF * acc;
}

// U2T[h][m][g*32+s] = sum_d values[s, h*64+d] * Wo[(g*64+d)*DM + m]
__global__ void k_U2(const float* __restrict__ Wo) {
    int hg = blockIdx.y;
    int h = hg >> 4, g = hg & 15;
    int m = blockIdx.x * 256 + threadIdx.x;
    __shared__ float vs[SPAT * HDM];
    for (int idx = threadIdx.x; idx < SPAT * HDM; idx += 256) {
        int s = idx >> 6, d = idx & 63;
        vs[idx] = g_values[s * DM + h * HDM + d];
    }
    __syncthreads();
    float acc[SPAT];
#pragma unroll
    for (int s = 0; s < SPAT; s++) acc[s] = 0.f;
    for (int d = 0; d < HDM; d++) {
        float w = Wo[(size_t)(g * HDM + d) * DM + m];
#pragma unroll
        for (int s = 0; s < SPAT; s++) acc[s] = fmaf(vs[s * HDM + d], w, acc[s]);
    }
    size_t base = ((size_t)(h << 10) + m) * NSC + (g << 5);
#pragma unroll
    for (int s = 0; s < SPAT; s++) {
        __nv_bfloat16 hi = __float2bfloat16(acc[s]);
        g_u2thi[base + s] = hi;
        g_u2tlo[base + s] = __float2bfloat16(acc[s] - __bfloat162float(hi));
    }
}

// query -> bf16 hi/lo
__global__ void k_convq(const float* __restrict__ q) {
    const size_t n4 = (size_t)NROWS * DM / 4;
    const float4* Q4 = (const float4*)q;
    __nv_bfloat162* Hi = (__nv_bfloat162*)g_qhi;
    __nv_bfloat162* Lo = (__nv_bfloat162*)g_qlo;
    size_t stride = (size_t)gridDim.x * blockDim.x;
    for (size_t j = (size_t)blockIdx.x * blockDim.x + threadIdx.x; j < n4; j += stride) {
        float4 v = Q4[j];
        __nv_bfloat16 hx = __float2bfloat16(v.x), hy = __float2bfloat16(v.y);
        __nv_bfloat16 hz = __float2bfloat16(v.z), hw = __float2bfloat16(v.w);
        Hi[2 * j]     = __halves2bfloat162(hx, hy);
        Hi[2 * j + 1] = __halves2bfloat162(hz, hw);
        Lo[2 * j]     = __halves2bfloat162(__float2bfloat16(v.x - __bfloat162float(hx)),
                                           __float2bfloat16(v.y - __bfloat162float(hy)));
        Lo[2 * j + 1] = __halves2bfloat162(__float2bfloat16(v.z - __bfloat162float(hz)),
                                           __float2bfloat16(v.w - __bfloat162float(hw)));
    }
}

// ======================= HMMA split GEMM ===================================
// which==0: scores[32768,512]  = q (hi/lo)[32768,1024] x PT^T   + sbias
// which==1: out[32768,1024]    = a2 (hi/lo)[32768,512] x U2T[h]^T + bo
// Tiles 128x128, BK=64, 256 thr, warps 4(m) x 2(n): each warp 32x64.
#define T_AHI 0
#define T_ALO 16384
#define T_BHI 32768
#define T_BLO 49152
#define BUFSZ 65536
#define SMEM_SZ (2 * BUFSZ + 1024)

__global__ void __launch_bounds__(256) gemm_tc(int which, float* __restrict__ Cext,
                                               const float* __restrict__ bo) {
    extern __shared__ char smraw[];
    uint32_t sb = (smem_u32(smraw) + 1023u) & ~1023u;
    int tid = threadIdx.x;
    int wid = tid >> 5, lane = tid & 31;
    int warp_m = (wid & 3) * 32;
    int warp_n = (wid >> 2) * 64;
    size_t m0 = (size_t)blockIdx.y * 128;
    size_t n0 = (size_t)blockIdx.x * 128;

    const __nv_bfloat16 *Ahi, *Alo, *Bhi, *Blo;
    const float* bias;
    float* C;
    int K, ldc;
    if (which == 0) {
        Ahi = g_qhi; Alo = g_qlo; Bhi = g_pthi; Blo = g_ptlo;
        bias = g_sbias; C = g_scores; K = DM; ldc = NSC;
    } else {
        size_t hoff = ((size_t)((m0 & 4095) >> 8)) * DM * NSC;
        Ahi = g_a2hi; Alo = g_a2lo; Bhi = g_u2thi + hoff; Blo = g_u2tlo + hoff;
        bias = bo; C = Cext; K = NSC; ldc = DM;
    }

    float acc[2][8][4];
#pragma unroll
    for (int mt = 0; mt < 2; mt++)
#pragma unroll
        for (int nt = 0; nt < 8; nt++)
#pragma unroll
            for (int r = 0; r < 4; r++) acc[mt][nt][r] = 0.f;

    const int nch = K >> 6;

    // load chunk ch into buffer buf
    auto issue_loads = [&](int ch, int buf) {
        uint32_t base = sb + buf * BUFSZ;
#pragma unroll
        for (int it = 0; it < 4; it++) {
            int idx = it * 256 + tid;            // 0..1023
            int row = idx >> 3;
            int kb  = idx & 7;
            uint32_t sw = swz((uint32_t)(row << 7) + (uint32_t)(kb << 4));
            size_t goff = (size_t)row * K + (ch << 6) + (kb << 3);
            CP16(base + T_AHI + sw, Ahi + m0 * K + goff);
            CP16(base + T_ALO + sw, Alo + m0 * K + goff);
            CP16(base + T_BHI + sw, Bhi + n0 * K + goff);
            CP16(base + T_BLO + sw, Blo + n0 * K + goff);
        }
        CP_COMMIT();
    };

    issue_loads(0, 0);
    int buf = 0;
    for (int ch = 0; ch < nch; ch++) {
        if (ch + 1 < nch) {
            issue_loads(ch + 1, buf ^ 1);
            CP_WAIT(1);
        } else {
            CP_WAIT(0);
        }
        __syncthreads();

        uint32_t base = sb + buf * BUFSZ;
#pragma unroll
        for (int ks = 0; ks < 4; ks++) {
            uint32_t ah[2][4], al[2][4], bh[8][2], bl[8][2];
            // A fragments: lanes 0-15 -> rows 0..15 (k-half 0), 16-31 -> k-half 1
#pragma unroll
            for (int mt = 0; mt < 2; mt++) {
                int row = warp_m + mt * 16 + (lane & 15);
                int kb8 = ks * 2 + (lane >> 4);
                uint32_t sw = swz((uint32_t)(row << 7) + (uint32_t)(kb8 << 4));
                LDSM4(ah[mt], base + T_AHI + sw);
                LDSM4(al[mt], base + T_ALO + sw);
            }
            // B fragments: x4 covers 2 n-tiles (16 n-rows) x k16
#pragma unroll
            for (int nt2 = 0; nt2 < 4; nt2++) {
                int nrow = warp_n + nt2 * 16 + ((lane >> 4) & 1) * 8 + (lane & 7);
                int kb8  = ks * 2 + ((lane >> 3) & 1);
                uint32_t sw = swz((uint32_t)(nrow << 7) + (uint32_t)(kb8 << 4));
                uint32_t t4[4];
                LDSM4(t4, base + T_BHI + sw);
                bh[2 * nt2][0] = t4[0]; bh[2 * nt2][1] = t4[1];
                bh[2 * nt2 + 1][0] = t4[2]; bh[2 * nt2 + 1][1] = t4[3];
                LDSM4(t4, base + T_BLO + sw);
                bl[2 * nt2][0] = t4[0]; bl[2 * nt2][1] = t4[1];
                bl[2 * nt2 + 1][0] = t4[2]; bl[2 * nt2 + 1][1] = t4[3];
            }
#pragma unroll
            for (int mt = 0; mt < 2; mt++)
#pragma unroll
                for (int nt = 0; nt < 8; nt++) {
                    MMA16816(acc[mt][nt], ah[mt], bh[nt]);
                    MMA16816(acc[mt][nt], ah[mt], bl[nt]);
                    MMA16816(acc[mt][nt], al[mt], bh[nt]);
                }
        }
        __syncthreads();
        buf ^= 1;
    }

    // epilogue: thread t: rows = warp_m + mt*16 + lane/4 (+8), cols = warp_n + nt*8 + 2*(lane%4)
    int r0 = lane >> 2;
    int c0 = (lane & 3) * 2;
#pragma unroll
    for (int mt = 0; mt < 2; mt++) {
#pragma unroll
        for (int nt = 0; nt < 8; nt++) {
            size_t col = n0 + warp_n + nt * 8 + c0;
            float2 bv = *(const float2*)(bias + col);
            size_t row0 = m0 + warp_m + mt * 16 + r0;
            float2 o0 = { acc[mt][nt][0] + bv.x, acc[mt][nt][1] + bv.y };
            *(float2*)(C + row0 * ldc + col) = o0;
            float2 o1 = { acc[mt][nt][2] + bv.x, acc[mt][nt][3] + bv.y };
            *(float2*)(C + (row0 + 8) * ldc + col) = o1;
        }
    }
}

// ================ sparsemax + split + mix-gather write =====================
__global__ void k_sparsemax() {
    int W = blockIdx.x * 8 + (threadIdx.x >> 5);   // W = r*16 + h
    int lane = threadIdx.x & 31;
    size_t base = (size_t)W * 32;
    float z = g_scores[base + lane];
    float v = z;
#pragma unroll
    for (int k = 2; k <= 32; k <<= 1)
#pragma unroll
        for (int j = k >> 1; j > 0; j >>= 1) {
            float o = __shfl_xor_sync(0xffffffffu, v, j);
            bool up = ((lane & k) == 0) == ((lane & j) == 0);
            v = up ? fmaxf(v, o) : fminf(v, o);
        }
    float cum = v;
#pragma unroll
    for (int d = 1; d < 32; d <<= 1) {
        float tt = __shfl_up_sync(0xffffffffu, cum, d);
        if (lane >= d) cum += tt;
    }
    bool sup = (1.0f + (float)(lane + 1) * v) > cum;
    unsigned bal = __ballot_sync(0xffffffffu, sup);
    int ksup = __popc(bal);
    float cumsel = __shfl_sync(0xffffffffu, cum, ksup - 1);
    float tau = (cumsel - 1.0f) / (float)ksup;
    float p = fmaxf(z - tau, 0.0f);

    int r = W >> 4, h = W & 15;
    int b = r >> 12, l = r & 4095;
    size_t drow = ((size_t)b << 12) + (h << 8) + (l >> 4);
    size_t didx = drow * NSC + ((size_t)(l & 15) << 5) + lane;
    __nv_bfloat16 hi = __float2bfloat16(p);
    g_a2hi[didx] = hi;
    g_a2lo[didx] = __float2bfloat16(p - __bfloat162float(hi));
}

// ---------------------------------------------------------------------------
extern "C" void kernel_launch(void* const* d_in, const int* in_sizes, int n_in,
                              void* d_out, int out_size) {
    (void)in_sizes; (void)n_in; (void)out_size;
    const float* query = (const float*)d_in[0];
    const float* kp    = (const float*)d_in[1];
    const float* Wq    = (const float*)d_in[2];
    const float* bq    = (const float*)d_in[3];
    const float* Wk    = (const float*)d_in[4];
    const float* bk    = (const float*)d_in[5];
    const float* Wv    = (const float*)d_in[6];
    const float* bv    = (const float*)d_in[7];
    const float* Wo    = (const float*)d_in[8];
    const float* bo    = (const float*)d_in[9];
    float* out = (float*)d_out;

    static bool attr_done = false;
    if (!attr_done) {
        cudaFuncSetAttribute(gemm_tc, cudaFuncAttributeMaxDynamicSharedMemorySize, SMEM_SZ);
        attr_done = true;
    }

    k_convq <<<4096, 256>>>(query);
    k_keys  <<<dim3(4, SPAT), 256>>>(kp, Wk, bk);
    k_values<<<dim3(4, SPAT), 256>>>(Wv, bv);
    k_P     <<<DM, 512>>>(Wq);
    k_sbias <<<1, 512>>>(bq);
    k_U2    <<<dim3(4, 256), 256>>>(Wo);

    gemm_tc<<<dim3(NSC / 128, NROWS / 128), 256, SMEM_SZ>>>(0, nullptr, nullptr);
    k_sparsemax<<<(NROWS * NHD) / 8, 256>>>();
    gemm_tc<<<dim3(DM / 128, NROWS / 128), 256, SMEM_SZ>>>(1, out, bo);
}